// round 3
// baseline (speedup 1.0000x reference)
#include <cuda_runtime.h>

// MMSolver: 128x128 LLG micromagnetics, 356 RK4 steps (100 relax + 256 driven).
// Persistent kernel, 128 CTAs (one 8x16 tile each), software global barrier.
// Superstep = 2 RK4 steps (8 stencil stages) on a halo-8 region (24x32) in smem.
// R2 changes vs R1:
//   * Each thread owns a 1x2 j-strip (384 threads = 12 warps, 3/SMSP balanced).
//   * N/S halo via LDS.64, one j-neighbor in-register, only strip-end scalars.
//   * No shrink predicates: all region cells computed every stage; cells outside
//     the shrinking valid window produce garbage that is provably never read
//     by any cell that remains valid (valid window shrinks by 1 per stage).
//   * Domain edge-replicate BC via static per-thread selects.

#define NXY 128
#define TI 8
#define TJ 16
#define HALO 8
#define RI (TI + 2*HALO)      // 24
#define RJ (TJ + 2*HALO)      // 32
#define RSTR 34               // padded row stride (floats), 8B-align friendly
#define NSTRIP (RJ/2)         // 16 strips of 2 cells
#define NCTA 128
#define NTHREADS (RI*NSTRIP)  // 384
#define RELAXN 100
#define TSIG 256
#define NSTEPS (RELAXN + TSIG)  // 356
#define NSS (NSTEPS/2)          // 178 supersteps

#define HH      0.017595f                          // GAMMA*DT
#define CS      0.001f                             // C_SOT
#define MU0F    1.2566370614359173e-06f
#define CEXN    (2.0f*1.3e-11f/(5e-9f*5e-9f))     // 2*A_EX/DX^2

__device__ float g_m[3][NXY][NXY];
__device__ unsigned int g_bar_count;
__device__ unsigned int g_bar_gen;

__global__ void __launch_bounds__(NTHREADS, 1)
mm_kernel(const float* __restrict__ signal,
          const float* __restrict__ B_ext,
          const float* __restrict__ Msat,
          const int*   __restrict__ src_idx,
          const int*   __restrict__ probe_idx,
          float*       __restrict__ out)
{
    __shared__ float sm[2][3][RI][RSTR];
    __shared__ unsigned int s_gen;

    const int tid = threadIdx.x;
    if (tid == 0) s_gen = *(volatile unsigned int*)&g_bar_gen;

    const int r  = tid >> 4;          // region row 0..23
    const int c  = tid & 15;          // strip 0..15
    const int j0 = c * 2;             // region col of cell 0
    const int bi = blockIdx.x >> 3;
    const int bj = blockIdx.x & 7;
    const int gi  = bi * TI - HALO + r;
    const int gjb = bj * TJ - HALO + j0;

    const int gci = min(max(gi, 0), NXY - 1);
    const int gc0 = min(max(gjb,     0), NXY - 1);
    const int gc1 = min(max(gjb + 1, 0), NXY - 1);
    const int gg0 = gci * NXY + gc0;
    const int gg1 = gci * NXY + gc1;

    // edge-replicate BC selects (static per thread)
    const bool ownN = (gi <= 0);
    const bool ownS = (gi >= NXY - 1);
    const bool ownW = (gjb == 0);          // j even: domain col 0 is a strip start
    const bool ownE = (gjb + 1 == NXY - 1);// domain col 127 is a strip end
    const int rN = max(r - 1, 0);
    const int rS = min(r + 1, RI - 1);
    const int jW = max(j0 - 1, 0);
    const int jE = min(j0 + 2, RJ - 1);

    // per-cell statics (clamped loads; out-of-domain cells are garbage-tolerated)
    float Bx[2], By[2], Bz[2], ms[2], cex[2], dem[2];
    Bx[0] = B_ext[gg0];                 Bx[1] = B_ext[gg1];
    By[0] = B_ext[NXY*NXY + gg0];       By[1] = B_ext[NXY*NXY + gg1];
    Bz[0] = B_ext[2*NXY*NXY + gg0];     Bz[1] = B_ext[2*NXY*NXY + gg1];
    ms[0] = Msat[gg0];                  ms[1] = Msat[gg1];
    cex[0] = CEXN / ms[0];              cex[1] = CEXN / ms[1];
    dem[0] = -MU0F * ms[0];             dem[1] = -MU0F * ms[1];

    // src slot per cell: last match wins (JAX .set scatter semantics)
    int src[2] = {-1, -1};
    #pragma unroll
    for (int s = 0; s < 2; s++) {
        const int si = src_idx[2*s], sj = src_idx[2*s + 1];
        if (si == gi && sj == gjb)     src[0] = s;
        if (si == gi && sj == gjb + 1) src[1] = s;
    }

    const bool is_tile = (r >= HALO && r < HALO + TI && j0 >= HALO && j0 < HALO + TJ);
    int pm[2] = {0, 0};
    if (is_tile) {
        #pragma unroll
        for (int p = 0; p < 4; p++) {
            const int pi = probe_idx[2*p], pj = probe_idx[2*p + 1];
            if (pi == gi && pj == gjb)     pm[0] |= 1 << p;
            if (pi == gi && pj == gjb + 1) pm[1] |= 1 << p;
        }
    }
    float pb[2] = {0.f, 0.f};

    __syncthreads();
    unsigned int gen = s_gen;

    float cm[3][2], m0[3][2], ac[3][2];
    int cur = 0;
    float* gm = &g_m[0][0][0];

    for (int ss = 0; ss < NSS; ++ss) {
        // ---- load region from global ----
        if (ss == 0) {
            #pragma unroll
            for (int l = 0; l < 2; l++) { cm[0][l] = 0.f; cm[1][l] = 1.f; cm[2][l] = 0.f; }
        } else {
            cm[0][0] = __ldcg(gm + gg0);               cm[0][1] = __ldcg(gm + gg1);
            cm[1][0] = __ldcg(gm + NXY*NXY + gg0);     cm[1][1] = __ldcg(gm + NXY*NXY + gg1);
            cm[2][0] = __ldcg(gm + 2*NXY*NXY + gg0);   cm[2][1] = __ldcg(gm + 2*NXY*NXY + gg1);
        }
        #pragma unroll
        for (int m = 0; m < 3; m++) {
            float2 v; v.x = cm[m][0]; v.y = cm[m][1];
            *reinterpret_cast<float2*>(&sm[cur][m][r][j0]) = v;
            m0[m][0] = cm[m][0]; m0[m][1] = cm[m][1];
        }
        __syncthreads();

        #pragma unroll
        for (int s = 0; s < 2; ++s) {
            const int step = ss * 2 + s;
            const bool relax = (step < RELAXN);
            const float alpha = relax ? 0.5f : 0.02f;
            const float ncoef = -1.0f / (1.0f + alpha * alpha);

            float bzd[2]; bzd[0] = Bz[0]; bzd[1] = Bz[1];
            if (!relax) {
                #pragma unroll
                for (int l = 0; l < 2; l++)
                    if (src[l] >= 0)
                        bzd[l] = __ldg(&signal[(step - RELAXN) * 2 + src[l]]);
            }
            #pragma unroll
            for (int m = 0; m < 3; m++) { ac[m][0] = 0.f; ac[m][1] = 0.f; }

            #pragma unroll
            for (int st = 0; st < 4; ++st) {
                const int nxt = cur ^ 1;
                float lap[3][2];
                #pragma unroll
                for (int m = 0; m < 3; m++) {
                    const float2 N2 = *reinterpret_cast<const float2*>(&sm[cur][m][rN][j0]);
                    const float2 S2 = *reinterpret_cast<const float2*>(&sm[cur][m][rS][j0]);
                    const float wv = sm[cur][m][r][jW];
                    const float ev = sm[cur][m][r][jE];
                    const float n0 = ownN ? cm[m][0] : N2.x;
                    const float n1 = ownN ? cm[m][1] : N2.y;
                    const float s0 = ownS ? cm[m][0] : S2.x;
                    const float s1 = ownS ? cm[m][1] : S2.y;
                    const float w0 = ownW ? cm[m][0] : wv;
                    const float e1 = ownE ? cm[m][1] : ev;
                    lap[m][0] = n0 + s0 + w0 + cm[m][1] - 4.f * cm[m][0];
                    lap[m][1] = n1 + s1 + cm[m][0] + e1 - 4.f * cm[m][1];
                }
                #pragma unroll
                for (int l = 0; l < 2; l++) {
                    const float mx = cm[0][l], my = cm[1][l], mz = cm[2][l];
                    const float bx = Bx[l]  + cex[l] * lap[0][l];
                    const float by = By[l]  + cex[l] * lap[1][l];
                    const float bz = bzd[l] + cex[l] * lap[2][l] + dem[l] * mz;
                    const float cx = my * bz - mz * by;
                    const float cy = mz * bx - mx * bz;
                    const float cz = mx * by - my * bx;
                    const float dx = my * cz - mz * cy;
                    const float dy = mz * cx - mx * cz;
                    const float dz = mx * cy - my * cx;
                    const float kx =  CS * (mx * my)           + ncoef * (cx + alpha * dx);
                    const float ky = -CS * (mx * mx + mz * mz) + ncoef * (cy + alpha * dy);
                    const float kz =  CS * (my * mz)           + ncoef * (cz + alpha * dz);
                    if (st < 3) {
                        const float w = (st == 0) ? 1.f : 2.f;
                        ac[0][l] += w * kx; ac[1][l] += w * ky; ac[2][l] += w * kz;
                        const float cc = (st == 2) ? HH : (0.5f * HH);
                        cm[0][l] = m0[0][l] + cc * kx;
                        cm[1][l] = m0[1][l] + cc * ky;
                        cm[2][l] = m0[2][l] + cc * kz;
                    } else {
                        cm[0][l] = m0[0][l] + (HH / 6.f) * (ac[0][l] + kx);
                        cm[1][l] = m0[1][l] + (HH / 6.f) * (ac[1][l] + ky);
                        cm[2][l] = m0[2][l] + (HH / 6.f) * (ac[2][l] + kz);
                        m0[0][l] = cm[0][l]; m0[1][l] = cm[1][l]; m0[2][l] = cm[2][l];
                    }
                }
                if (!(s == 1 && st == 3)) {   // last stage of superstep: smem never re-read
                    #pragma unroll
                    for (int m = 0; m < 3; m++) {
                        float2 v; v.x = cm[m][0]; v.y = cm[m][1];
                        *reinterpret_cast<float2*>(&sm[nxt][m][r][j0]) = v;
                    }
                }
                cur = nxt;
                __syncthreads();
            }

            // probe readout (tile cells valid after every step)
            if (pm[0] | pm[1]) {
                if (step == RELAXN - 1) {
                    pb[0] = m0[2][0]; pb[1] = m0[2][1];
                } else if (step >= RELAXN) {
                    const int t = step - RELAXN;
                    #pragma unroll
                    for (int l = 0; l < 2; l++) {
                        if (pm[l]) {
                            const float v = (m0[2][l] - pb[l]) * ms[l];
                            #pragma unroll
                            for (int p = 0; p < 4; p++)
                                if ((pm[l] >> p) & 1) out[t * 4 + p] = v;
                        }
                    }
                }
            }
        }

        // ---- write back owned tile (strip fully inside tile or fully outside) ----
        if (is_tile) {
            const int g = gi * NXY + gjb;
            float2 v0; v0.x = m0[0][0]; v0.y = m0[0][1];
            float2 v1; v1.x = m0[1][0]; v1.y = m0[1][1];
            float2 v2; v2.x = m0[2][0]; v2.y = m0[2][1];
            __stcg(reinterpret_cast<float2*>(gm + g), v0);
            __stcg(reinterpret_cast<float2*>(gm + NXY*NXY + g), v1);
            __stcg(reinterpret_cast<float2*>(gm + 2*NXY*NXY + g), v2);
        }

        // ---- global software barrier (128 CTAs co-resident on 148 SMs) ----
        if (ss < NSS - 1) {
            __syncthreads();
            if (tid == 0) {
                __threadfence();
                if (atomicAdd(&g_bar_count, 1u) == NCTA - 1) {
                    atomicExch(&g_bar_count, 0u);
                    __threadfence();
                    atomicExch(&g_bar_gen, gen + 1u);
                } else {
                    while (*(volatile unsigned int*)&g_bar_gen == gen) { }
                    __threadfence();
                }
            }
            gen++;
            __syncthreads();
        }
    }
}

extern "C" void kernel_launch(void* const* d_in, const int* in_sizes, int n_in,
                              void* d_out, int out_size)
{
    (void)in_sizes; (void)n_in; (void)out_size;
    mm_kernel<<<NCTA, NTHREADS>>>(
        (const float*)d_in[0],   // signal (1,256,2)
        (const float*)d_in[1],   // B_ext  (1,3,128,128)
        (const float*)d_in[2],   // Msat   (1,1,128,128)
        (const int*)d_in[3],     // src_idx (2,2)
        (const int*)d_in[4],     // probe_idx (4,2)
        (float*)d_out);          // (1,256,4)
}

// round 4
// speedup vs baseline: 1.0244x; 1.0244x over previous
#include <cuda_runtime.h>

// MMSolver: 128x128 LLG micromagnetics, 356 RK4 steps (100 relax + 256 driven).
// Persistent kernel, 128 CTAs (8x16 tile each), software global barrier.
// Superstep = 2 RK4 steps (8 stencil stages) on a halo-8 region (24x32) in smem.
// R3: warp = one region row (32 lanes along j). W/E neighbors come from warp
// shuffles (no smem); only N/S rows go through shared memory (6 LDS/stage vs 12).
// No shrink predicates: all region cells computed every stage; dead-halo garbage
// is never read by any still-valid cell. Domain edge-replicate BC via clamped
// row indices (N/S) and FSELs (W/E).

#define NXY 128
#define TI 8
#define TJ 16
#define HALO 8
#define RI (TI + 2*HALO)      // 24
#define RJ (TJ + 2*HALO)      // 32  == warp width
#define NCTA 128
#define NTHREADS (RI*RJ)      // 768
#define RELAXN 100
#define TSIG 256
#define NSTEPS (RELAXN + TSIG)  // 356
#define NSS (NSTEPS/2)          // 178

#define HH      0.017595f                        // GAMMA*DT
#define CS      0.001f                           // C_SOT
#define MU0F    1.2566370614359173e-06f
#define CEXN    (2.0f*1.3e-11f/(5e-9f*5e-9f))   // 2*A_EX/DX^2

__device__ float g_m[3][NXY][NXY];
__device__ unsigned int g_bar_count;
__device__ unsigned int g_bar_gen;

__global__ void __launch_bounds__(NTHREADS, 1)
mm_kernel(const float* __restrict__ signal,
          const float* __restrict__ B_ext,
          const float* __restrict__ Msat,
          const int*   __restrict__ src_idx,
          const int*   __restrict__ probe_idx,
          float*       __restrict__ out)
{
    __shared__ float sm[2][3][RI][RJ];   // stride 32 -> conflict-free row loads
    __shared__ unsigned int s_gen;
    const unsigned FULL = 0xFFFFFFFFu;

    const int tid = threadIdx.x;
    if (tid == 0) s_gen = *(volatile unsigned int*)&g_bar_gen;

    const int ri = tid >> 5;        // region row 0..23 (warp id)
    const int rj = tid & 31;        // region col 0..31 (lane)
    const int bi = blockIdx.x >> 3; // 0..15
    const int bj = blockIdx.x & 7;  // 0..7
    const int gi = bi * TI - HALO + ri;
    const int gj = bj * TJ - HALO + rj;

    const int gci = min(max(gi, 0), NXY - 1);
    const int gcj = min(max(gj, 0), NXY - 1);
    const int gg  = gci * NXY + gcj;

    // N/S region row indices: clamped at region edge (garbage-safe) and at the
    // DOMAIN edge (edge-replicate BC -> read own row, which holds own value).
    const int riN = (gi <= 0)       ? ri : max(ri - 1, 0);
    const int riS = (gi >= NXY - 1) ? ri : min(ri + 1, RI - 1);
    // W/E domain-edge ownership (shuffle result overridden by own value)
    const bool ownW = (gj == 0);
    const bool ownE = (gj == NXY - 1);

    // per-cell statics (clamped loads; halo-outside cells hold consistent junk)
    const float Bx  = B_ext[gg];
    const float By  = B_ext[NXY*NXY + gg];
    const float Bzs = B_ext[2*NXY*NXY + gg];
    const float msat = Msat[gg];
    const float cex  = CEXN / msat;
    const float dem  = -MU0F * msat;

    // src slot: last match wins (JAX .set scatter semantics)
    int srcslot = -1;
    #pragma unroll
    for (int s = 0; s < 2; s++)
        if (src_idx[2*s] == gi && src_idx[2*s + 1] == gj) srcslot = s;

    const bool is_tile = (ri >= HALO && ri < HALO + TI && rj >= HALO && rj < HALO + TJ);
    int probemask = 0;
    if (is_tile) {
        #pragma unroll
        for (int p = 0; p < 4; p++)
            if (probe_idx[2*p] == gi && probe_idx[2*p + 1] == gj) probemask |= 1 << p;
    }
    float probe_base = 0.f;

    __syncthreads();
    unsigned int gen = s_gen;

    float cmx, cmy, cmz;    // current stage value
    float m0x, m0y, m0z;    // value at start of current RK4 step
    int cur = 0;
    float* gm = &g_m[0][0][0];

    for (int ss = 0; ss < NSS; ++ss) {
        // ---- load region ----
        if (ss == 0) {
            cmx = 0.f; cmy = 1.f; cmz = 0.f;
        } else {
            cmx = __ldcg(gm + gg);
            cmy = __ldcg(gm + NXY*NXY + gg);
            cmz = __ldcg(gm + 2*NXY*NXY + gg);
        }
        sm[cur][0][ri][rj] = cmx;
        sm[cur][1][ri][rj] = cmy;
        sm[cur][2][ri][rj] = cmz;
        m0x = cmx; m0y = cmy; m0z = cmz;

        // preload driven-field z values for the 2 steps of this superstep
        float bzstep[2]; bzstep[0] = Bzs; bzstep[1] = Bzs;
        {
            const int step0 = ss * 2;
            if (srcslot >= 0) {
                #pragma unroll
                for (int s = 0; s < 2; s++) {
                    const int step = step0 + s;
                    if (step >= RELAXN)
                        bzstep[s] = __ldg(&signal[(step - RELAXN) * 2 + srcslot]);
                }
            }
        }
        __syncthreads();

        #pragma unroll
        for (int s = 0; s < 2; ++s) {
            const int step = ss * 2 + s;
            const bool relax = (step < RELAXN);
            const float alpha = relax ? 0.5f : 0.02f;
            const float ncoef = -1.0f / (1.0f + alpha * alpha);
            const float bzd = bzstep[s];

            float ax = 0.f, ay = 0.f, az = 0.f;   // k1 + 2k2 + 2k3

            #pragma unroll
            for (int st = 0; st < 4; ++st) {
                const int nxt = cur ^ 1;
                // --- neighbors ---
                const float nx = sm[cur][0][riN][rj];
                const float ny = sm[cur][1][riN][rj];
                const float nz = sm[cur][2][riN][rj];
                const float sx_ = sm[cur][0][riS][rj];
                const float sy_ = sm[cur][1][riS][rj];
                const float sz_ = sm[cur][2][riS][rj];
                float wx = __shfl_up_sync(FULL, cmx, 1);
                float wy = __shfl_up_sync(FULL, cmy, 1);
                float wz = __shfl_up_sync(FULL, cmz, 1);
                float ex = __shfl_down_sync(FULL, cmx, 1);
                float ey = __shfl_down_sync(FULL, cmy, 1);
                float ez = __shfl_down_sync(FULL, cmz, 1);
                wx = ownW ? cmx : wx;  wy = ownW ? cmy : wy;  wz = ownW ? cmz : wz;
                ex = ownE ? cmx : ex;  ey = ownE ? cmy : ey;  ez = ownE ? cmz : ez;

                const float lx = (nx + sx_) + (wx + ex) - 4.f * cmx;
                const float ly = (ny + sy_) + (wy + ey) - 4.f * cmy;
                const float lz = (nz + sz_) + (wz + ez) - 4.f * cmz;

                const float bx = Bx  + cex * lx;
                const float by = By  + cex * ly;
                const float bz = bzd + cex * lz + dem * cmz;
                // c = m x B
                const float cx = cmy * bz - cmz * by;
                const float cy = cmz * bx - cmx * bz;
                const float cz = cmx * by - cmy * bx;
                // d = m x c
                const float dx = cmy * cz - cmz * cy;
                const float dy = cmz * cx - cmx * cz;
                const float dz = cmx * cy - cmy * cx;
                // k = sot + ncoef*(c + alpha*d)
                const float kx =  CS * (cmx * cmy)             + ncoef * (cx + alpha * dx);
                const float ky = -CS * (cmx * cmx + cmz * cmz) + ncoef * (cy + alpha * dy);
                const float kz =  CS * (cmy * cmz)             + ncoef * (cz + alpha * dz);

                if (st < 3) {
                    const float w = (st == 0) ? 1.f : 2.f;
                    ax += w * kx; ay += w * ky; az += w * kz;
                    const float cc = (st == 2) ? HH : (0.5f * HH);
                    cmx = m0x + cc * kx;
                    cmy = m0y + cc * ky;
                    cmz = m0z + cc * kz;
                } else {
                    cmx = m0x + (HH / 6.f) * (ax + kx);
                    cmy = m0y + (HH / 6.f) * (ay + ky);
                    cmz = m0z + (HH / 6.f) * (az + kz);
                    m0x = cmx; m0y = cmy; m0z = cmz;
                }
                if (!(s == 1 && st == 3)) {   // final stage result never re-read from smem
                    sm[nxt][0][ri][rj] = cmx;
                    sm[nxt][1][ri][rj] = cmy;
                    sm[nxt][2][ri][rj] = cmz;
                }
                cur = nxt;
                __syncthreads();
            }

            // probe readout (tile cells valid after every step; halo 8 = 2 steps)
            if (probemask) {
                if (step == RELAXN - 1) {
                    probe_base = m0z;
                } else if (step >= RELAXN) {
                    const float v = (m0z - probe_base) * msat;
                    const int t = step - RELAXN;
                    #pragma unroll
                    for (int p = 0; p < 4; p++)
                        if ((probemask >> p) & 1) out[t * 4 + p] = v;
                }
            }
        }

        // ---- write back owned tile ----
        if (is_tile) {
            const int g = gi * NXY + gj;
            __stcg(gm + g,               m0x);
            __stcg(gm + NXY*NXY + g,     m0y);
            __stcg(gm + 2*NXY*NXY + g,   m0z);
        }

        // ---- global software barrier (128 CTAs co-resident on 148 SMs) ----
        if (ss < NSS - 1) {
            __syncthreads();
            if (tid == 0) {
                __threadfence();
                if (atomicAdd(&g_bar_count, 1u) == NCTA - 1) {
                    atomicExch(&g_bar_count, 0u);
                    __threadfence();
                    atomicExch(&g_bar_gen, gen + 1u);
                } else {
                    while (*(volatile unsigned int*)&g_bar_gen == gen) { }
                    __threadfence();
                }
            }
            gen++;
            __syncthreads();
        }
    }
}

extern "C" void kernel_launch(void* const* d_in, const int* in_sizes, int n_in,
                              void* d_out, int out_size)
{
    (void)in_sizes; (void)n_in; (void)out_size;
    mm_kernel<<<NCTA, NTHREADS>>>(
        (const float*)d_in[0],   // signal (1,256,2)
        (const float*)d_in[1],   // B_ext  (1,3,128,128)
        (const float*)d_in[2],   // Msat   (1,1,128,128)
        (const int*)d_in[3],     // src_idx (2,2)
        (const int*)d_in[4],     // probe_idx (4,2)
        (float*)d_out);          // (1,256,4)
}

// round 5
// speedup vs baseline: 1.2570x; 1.2270x over previous
#include <cuda_runtime.h>

// MMSolver: 128x128 LLG micromagnetics, 356 RK4 steps (100 relax + 256 driven).
// Persistent kernel, 128 CTAs (8x16 tile each). Superstep = 2 RK4 steps
// (8 stencil stages, halo 8) on a 24x32 region in smem (R1-proven body with
// shrink-predicated compute).
// R4: global software barrier replaced by NEIGHBOR-LOCAL dataflow sync:
//  * g_m is double-buffered; superstep ss writes buf[ss&1].
//  * After tile writeback, CTA releases flag[me] = base+ss+1.
//  * Before loading superstep ss, CTA waits for its 8 grid-neighbors' flags
//    >= base+ss. Mutual dependency bounds skew to 1 superstep -> 2 buffers ok.
//  * Flags are base-relative (own flag read at start) -> deterministic across
//    CUDA-graph replays without any reset.

#define NXY 128
#define TI 8
#define TJ 16
#define HALO 8
#define RI (TI + 2*HALO)      // 24
#define RJ (TJ + 2*HALO)      // 32
#define NCTA 128
#define NTHREADS (RI*RJ)      // 768
#define RELAXN 100
#define TSIG 256
#define NSTEPS (RELAXN + TSIG)  // 356
#define NSS (NSTEPS/2)          // 178
#define FSTR 32                 // flag pad: 128B per CTA flag

#define HH      0.017595f                        // GAMMA*DT
#define CS      0.001f                           // C_SOT
#define MU0F    1.2566370614359173e-06f
#define CEXN    (2.0f*1.3e-11f/(5e-9f*5e-9f))   // 2*A_EX/DX^2

__device__ float g_m[2][3][NXY][NXY];
__device__ unsigned int g_flag[NCTA * FSTR];

__global__ void __launch_bounds__(NTHREADS, 1)
mm_kernel(const float* __restrict__ signal,
          const float* __restrict__ B_ext,
          const float* __restrict__ Msat,
          const int*   __restrict__ src_idx,
          const int*   __restrict__ probe_idx,
          float*       __restrict__ out)
{
    __shared__ float sm[2][3][RI][RJ];
    __shared__ unsigned int s_base;

    const int tid = threadIdx.x;
    const int me  = blockIdx.x;
    if (tid == 0) s_base = *(volatile unsigned int*)&g_flag[me * FSTR];

    const int ri = tid >> 5;        // region row 0..23 (warp id)
    const int rj = tid & 31;        // region col 0..31 (lane)
    const int bi = me >> 3;         // 0..15
    const int bj = me & 7;          // 0..7
    const int gi = bi * TI - HALO + ri;
    const int gj = bj * TJ - HALO + rj;
    const bool in_dom = (gi >= 0 && gi < NXY && gj >= 0 && gj < NXY);
    const int gci = min(max(gi, 0), NXY - 1);
    const int gcj = min(max(gj, 0), NXY - 1);
    const int gg  = gci * NXY + gcj;

    // neighbor region indices, clamped at the DOMAIN boundary (edge-replicate)
    const int riN = (gi <= 0)       ? ri : ri - 1;
    const int riS = (gi >= NXY - 1) ? ri : ri + 1;
    const int rjW = (gj <= 0)       ? rj : rj - 1;
    const int rjE = (gj >= NXY - 1) ? rj : rj + 1;

    // 8-neighbor CTA index for dataflow sync (self if out of grid)
    int nbflag = me;
    {
        const int ndi[8] = {-1,-1,-1, 0, 0, 1, 1, 1};
        const int ndj[8] = {-1, 0, 1,-1, 1,-1, 0, 1};
        if (tid < 8) {
            const int nbi = bi + ndi[tid];
            const int nbj = bj + ndj[tid];
            if (nbi >= 0 && nbi < 16 && nbj >= 0 && nbj < 8)
                nbflag = nbi * 8 + nbj;
        }
    }

    // per-cell statics
    float Bx = 0.f, By = 0.f, Bzs = 0.f, cex = 0.f, dem = 0.f, msat = 0.f;
    if (in_dom) {
        Bx   = B_ext[gg];
        By   = B_ext[NXY*NXY + gg];
        Bzs  = B_ext[2*NXY*NXY + gg];
        msat = Msat[gg];
        cex  = CEXN / msat;
        dem  = -MU0F * msat;
    }

    // src slot: last match wins (JAX .set scatter semantics)
    int srcslot = -1;
    #pragma unroll
    for (int s = 0; s < 2; s++)
        if (src_idx[2*s] == gi && src_idx[2*s + 1] == gj) srcslot = s;

    const bool is_tile = (ri >= HALO && ri < HALO + TI && rj >= HALO && rj < HALO + TJ);
    int probemask = 0;
    if (is_tile && in_dom) {
        #pragma unroll
        for (int p = 0; p < 4; p++)
            if (probe_idx[2*p] == gi && probe_idx[2*p + 1] == gj) probemask |= 1 << p;
    }
    float probe_base = 0.f;

    // precomputed shrink-window predicate, one bit per stage q=0..7
    unsigned cmask = 0;
    #pragma unroll
    for (int q = 0; q < 8; q++)
        if (in_dom && ri > q && ri < RI - 1 - q && rj > q && rj < RJ - 1 - q)
            cmask |= 1u << q;

    __syncthreads();
    const unsigned base = s_base;

    float cmx, cmy, cmz;    // current stage value
    float m0x, m0y, m0z;    // value at start of current RK4 step
    int cur = 0;

    for (int ss = 0; ss < NSS; ++ss) {
        // ---- wait for neighbors (ss>=1), then load region ----
        if (ss == 0) {
            cmx = 0.f; cmy = 1.f; cmz = 0.f;   // m_init = y-hat
        } else {
            if (tid < 8) {
                const unsigned tgt = base + (unsigned)ss;
                while ((int)(*(volatile unsigned int*)&g_flag[nbflag * FSTR] - tgt) < 0) { }
                __threadfence();
            }
            __syncthreads();
            const float* gmr = &g_m[(ss - 1) & 1][0][0][0];
            cmx = __ldcg(gmr + gg);
            cmy = __ldcg(gmr + NXY*NXY + gg);
            cmz = __ldcg(gmr + 2*NXY*NXY + gg);
        }
        sm[cur][0][ri][rj] = cmx;
        sm[cur][1][ri][rj] = cmy;
        sm[cur][2][ri][rj] = cmz;
        m0x = cmx; m0y = cmy; m0z = cmz;

        // preload driven-field z for the 2 steps of this superstep
        float bzstep[2]; bzstep[0] = Bzs; bzstep[1] = Bzs;
        if (srcslot >= 0) {
            #pragma unroll
            for (int s = 0; s < 2; s++) {
                const int step = ss * 2 + s;
                if (step >= RELAXN)
                    bzstep[s] = __ldg(&signal[(step - RELAXN) * 2 + srcslot]);
            }
        }
        __syncthreads();

        #pragma unroll
        for (int s = 0; s < 2; ++s) {
            const int step = ss * 2 + s;
            const bool relax = (step < RELAXN);
            const float alpha = relax ? 0.5f : 0.02f;
            const float ncoef = -1.0f / (1.0f + alpha * alpha);
            const float bzd = bzstep[s];

            float ax = 0.f, ay = 0.f, az = 0.f;   // k1 + 2k2 + 2k3

            #pragma unroll
            for (int st = 0; st < 4; ++st) {
                const int q = s * 4 + st;
                const bool comp = (cmask >> q) & 1;
                const int nxt = cur ^ 1;
                if (comp) {
                    const float lx = sm[cur][0][riN][rj] + sm[cur][0][riS][rj]
                                   + sm[cur][0][ri][rjW] + sm[cur][0][ri][rjE] - 4.f * cmx;
                    const float ly = sm[cur][1][riN][rj] + sm[cur][1][riS][rj]
                                   + sm[cur][1][ri][rjW] + sm[cur][1][ri][rjE] - 4.f * cmy;
                    const float lz = sm[cur][2][riN][rj] + sm[cur][2][riS][rj]
                                   + sm[cur][2][ri][rjW] + sm[cur][2][ri][rjE] - 4.f * cmz;
                    const float bx = Bx  + cex * lx;
                    const float by = By  + cex * ly;
                    const float bz = bzd + cex * lz + dem * cmz;
                    // c = m x B
                    const float cx = cmy * bz - cmz * by;
                    const float cy = cmz * bx - cmx * bz;
                    const float cz = cmx * by - cmy * bx;
                    // d = m x c
                    const float dx = cmy * cz - cmz * cy;
                    const float dy = cmz * cx - cmx * cz;
                    const float dz = cmx * cy - cmy * cx;
                    // k = sot + ncoef*(c + alpha*d)
                    const float kx =  CS * (cmx * cmy)             + ncoef * (cx + alpha * dx);
                    const float ky = -CS * (cmx * cmx + cmz * cmz) + ncoef * (cy + alpha * dy);
                    const float kz =  CS * (cmy * cmz)             + ncoef * (cz + alpha * dz);

                    if (st < 3) {
                        const float w = (st == 0) ? 1.f : 2.f;
                        ax += w * kx; ay += w * ky; az += w * kz;
                        const float cc = (st == 2) ? HH : (0.5f * HH);
                        cmx = m0x + cc * kx;
                        cmy = m0y + cc * ky;
                        cmz = m0z + cc * kz;
                    } else {
                        cmx = m0x + (HH / 6.f) * (ax + kx);
                        cmy = m0y + (HH / 6.f) * (ay + ky);
                        cmz = m0z + (HH / 6.f) * (az + kz);
                        m0x = cmx; m0y = cmy; m0z = cmz;   // step complete
                    }
                    if (!(s == 1 && st == 3)) {   // final stage never re-read from smem
                        sm[nxt][0][ri][rj] = cmx;
                        sm[nxt][1][ri][rj] = cmy;
                        sm[nxt][2][ri][rj] = cmz;
                    }
                }
                cur = nxt;
                __syncthreads();
            }

            // probe readout (tile cells valid after every step)
            if (probemask) {
                if (step == RELAXN - 1) {
                    probe_base = m0z;
                } else if (step >= RELAXN) {
                    const float v = (m0z - probe_base) * msat;
                    const int t = step - RELAXN;
                    #pragma unroll
                    for (int p = 0; p < 4; p++)
                        if ((probemask >> p) & 1) out[t * 4 + p] = v;
                }
            }
        }

        // ---- write back owned tile (double-buffered), release flag ----
        {
            float* gmw = &g_m[ss & 1][0][0][0];
            if (is_tile) {
                const int g = gi * NXY + gj;
                __stcg(gmw + g,               m0x);
                __stcg(gmw + NXY*NXY + g,     m0y);
                __stcg(gmw + 2*NXY*NXY + g,   m0z);
            }
        }
        if (ss < NSS - 1) {
            __syncthreads();
            if (tid == 0) {
                __threadfence();
                atomicExch(&g_flag[me * FSTR], base + (unsigned)ss + 1u);
            }
        }
    }
}

extern "C" void kernel_launch(void* const* d_in, const int* in_sizes, int n_in,
                              void* d_out, int out_size)
{
    (void)in_sizes; (void)n_in; (void)out_size;
    mm_kernel<<<NCTA, NTHREADS>>>(
        (const float*)d_in[0],   // signal (1,256,2)
        (const float*)d_in[1],   // B_ext  (1,3,128,128)
        (const float*)d_in[2],   // Msat   (1,1,128,128)
        (const int*)d_in[3],     // src_idx (2,2)
        (const int*)d_in[4],     // probe_idx (4,2)
        (float*)d_out);          // (1,256,4)
}

// round 6
// speedup vs baseline: 1.2853x; 1.0225x over previous
#include <cuda_runtime.h>

// MMSolver: 128x128 LLG micromagnetics, 356 RK4 steps (100 relax + 256 driven).
// Persistent kernel, 128 CTAs (8x16 tile each). Superstep = 2 RK4 steps
// (8 stencil stages, halo 8) on a 24x32 region in smem, shrink-predicated.
// Neighbor-local dataflow sync (R4). R5: float4-packed smem state so each
// neighbor fetch is one LDS.128 (4 loads + 1 STS.128 per stage instead of
// 12 LDS.32 + 3 STS.32); final-stage CTA barrier removed.

#define NXY 128
#define TI 8
#define TJ 16
#define HALO 8
#define RI (TI + 2*HALO)      // 24
#define RJ (TJ + 2*HALO)      // 32
#define NCTA 128
#define NTHREADS (RI*RJ)      // 768
#define RELAXN 100
#define TSIG 256
#define NSTEPS (RELAXN + TSIG)  // 356
#define NSS (NSTEPS/2)          // 178
#define FSTR 32                 // flag pad: 128B per CTA flag

#define HH      0.017595f                        // GAMMA*DT
#define CS      0.001f                           // C_SOT
#define MU0F    1.2566370614359173e-06f
#define CEXN    (2.0f*1.3e-11f/(5e-9f*5e-9f))   // 2*A_EX/DX^2

__device__ float g_m[2][3][NXY][NXY];
__device__ unsigned int g_flag[NCTA * FSTR];

__global__ void __launch_bounds__(NTHREADS, 1)
mm_kernel(const float* __restrict__ signal,
          const float* __restrict__ B_ext,
          const float* __restrict__ Msat,
          const int*   __restrict__ src_idx,
          const int*   __restrict__ probe_idx,
          float*       __restrict__ out)
{
    __shared__ float4 sm[2][RI][RJ];     // (x,y,z,pad) per cell, 24 KB
    __shared__ unsigned int s_base;

    const int tid = threadIdx.x;
    const int me  = blockIdx.x;
    if (tid == 0) s_base = *(volatile unsigned int*)&g_flag[me * FSTR];

    const int ri = tid >> 5;        // region row 0..23 (warp id)
    const int rj = tid & 31;        // region col 0..31 (lane)
    const int bi = me >> 3;         // 0..15
    const int bj = me & 7;          // 0..7
    const int gi = bi * TI - HALO + ri;
    const int gj = bj * TJ - HALO + rj;
    const bool in_dom = (gi >= 0 && gi < NXY && gj >= 0 && gj < NXY);
    const int gci = min(max(gi, 0), NXY - 1);
    const int gcj = min(max(gj, 0), NXY - 1);
    const int gg  = gci * NXY + gcj;

    // neighbor region indices, clamped at the DOMAIN boundary (edge-replicate)
    const int riN = (gi <= 0)       ? ri : ri - 1;
    const int riS = (gi >= NXY - 1) ? ri : ri + 1;
    const int rjW = (gj <= 0)       ? rj : rj - 1;
    const int rjE = (gj >= NXY - 1) ? rj : rj + 1;

    // 8-neighbor CTA flag index for dataflow sync (self if out of grid)
    int nbflag = me;
    {
        const int ndi[8] = {-1,-1,-1, 0, 0, 1, 1, 1};
        const int ndj[8] = {-1, 0, 1,-1, 1,-1, 0, 1};
        if (tid < 8) {
            const int nbi = bi + ndi[tid];
            const int nbj = bj + ndj[tid];
            if (nbi >= 0 && nbi < 16 && nbj >= 0 && nbj < 8)
                nbflag = nbi * 8 + nbj;
        }
    }

    // per-cell statics
    float Bx = 0.f, By = 0.f, Bzs = 0.f, cex = 0.f, dem = 0.f, msat = 0.f;
    if (in_dom) {
        Bx   = B_ext[gg];
        By   = B_ext[NXY*NXY + gg];
        Bzs  = B_ext[2*NXY*NXY + gg];
        msat = Msat[gg];
        cex  = CEXN / msat;
        dem  = -MU0F * msat;
    }

    // src slot: last match wins (JAX .set scatter semantics)
    int srcslot = -1;
    #pragma unroll
    for (int s = 0; s < 2; s++)
        if (src_idx[2*s] == gi && src_idx[2*s + 1] == gj) srcslot = s;

    const bool is_tile = (ri >= HALO && ri < HALO + TI && rj >= HALO && rj < HALO + TJ);
    int probemask = 0;
    if (is_tile && in_dom) {
        #pragma unroll
        for (int p = 0; p < 4; p++)
            if (probe_idx[2*p] == gi && probe_idx[2*p + 1] == gj) probemask |= 1 << p;
    }
    float probe_base = 0.f;

    // precomputed shrink-window predicate, one bit per stage q=0..7
    unsigned cmask = 0;
    #pragma unroll
    for (int q = 0; q < 8; q++)
        if (in_dom && ri > q && ri < RI - 1 - q && rj > q && rj < RJ - 1 - q)
            cmask |= 1u << q;

    __syncthreads();
    const unsigned base = s_base;

    float cmx, cmy, cmz;    // current stage value
    float m0x, m0y, m0z;    // value at start of current RK4 step
    int cur = 0;

    for (int ss = 0; ss < NSS; ++ss) {
        // ---- wait for neighbors (ss>=1), then load region ----
        if (ss == 0) {
            cmx = 0.f; cmy = 1.f; cmz = 0.f;   // m_init = y-hat
        } else {
            if (tid < 8) {
                const unsigned tgt = base + (unsigned)ss;
                while ((int)(*(volatile unsigned int*)&g_flag[nbflag * FSTR] - tgt) < 0) { }
                __threadfence();
            }
            __syncthreads();
            const float* gmr = &g_m[(ss - 1) & 1][0][0][0];
            cmx = __ldcg(gmr + gg);
            cmy = __ldcg(gmr + NXY*NXY + gg);
            cmz = __ldcg(gmr + 2*NXY*NXY + gg);
        }
        sm[cur][ri][rj] = make_float4(cmx, cmy, cmz, 0.f);
        m0x = cmx; m0y = cmy; m0z = cmz;

        // preload driven-field z for the 2 steps of this superstep
        float bzstep[2]; bzstep[0] = Bzs; bzstep[1] = Bzs;
        if (srcslot >= 0) {
            #pragma unroll
            for (int s = 0; s < 2; s++) {
                const int step = ss * 2 + s;
                if (step >= RELAXN)
                    bzstep[s] = __ldg(&signal[(step - RELAXN) * 2 + srcslot]);
            }
        }
        __syncthreads();

        #pragma unroll
        for (int s = 0; s < 2; ++s) {
            const int step = ss * 2 + s;
            const bool relax = (step < RELAXN);
            const float alpha = relax ? 0.5f : 0.02f;
            const float ncoef = -1.0f / (1.0f + alpha * alpha);
            const float bzd = bzstep[s];

            float ax = 0.f, ay = 0.f, az = 0.f;   // k1 + 2k2 + 2k3

            #pragma unroll
            for (int st = 0; st < 4; ++st) {
                const int q = s * 4 + st;
                const bool comp = (cmask >> q) & 1;
                const int nxt = cur ^ 1;
                if (comp) {
                    const float4 vN = sm[cur][riN][rj];
                    const float4 vS = sm[cur][riS][rj];
                    const float4 vW = sm[cur][ri][rjW];
                    const float4 vE = sm[cur][ri][rjE];
                    const float lx = (vN.x + vS.x) + (vW.x + vE.x) - 4.f * cmx;
                    const float ly = (vN.y + vS.y) + (vW.y + vE.y) - 4.f * cmy;
                    const float lz = (vN.z + vS.z) + (vW.z + vE.z) - 4.f * cmz;
                    const float bx = Bx  + cex * lx;
                    const float by = By  + cex * ly;
                    const float bz = bzd + cex * lz + dem * cmz;
                    // c = m x B
                    const float cx = cmy * bz - cmz * by;
                    const float cy = cmz * bx - cmx * bz;
                    const float cz = cmx * by - cmy * bx;
                    // d = m x c
                    const float dx = cmy * cz - cmz * cy;
                    const float dy = cmz * cx - cmx * cz;
                    const float dz = cmx * cy - cmy * cx;
                    // k = sot + ncoef*(c + alpha*d)
                    const float kx =  CS * (cmx * cmy)             + ncoef * (cx + alpha * dx);
                    const float ky = -CS * (cmx * cmx + cmz * cmz) + ncoef * (cy + alpha * dy);
                    const float kz =  CS * (cmy * cmz)             + ncoef * (cz + alpha * dz);

                    if (st < 3) {
                        const float w = (st == 0) ? 1.f : 2.f;
                        ax += w * kx; ay += w * ky; az += w * kz;
                        const float cc = (st == 2) ? HH : (0.5f * HH);
                        cmx = m0x + cc * kx;
                        cmy = m0y + cc * ky;
                        cmz = m0z + cc * kz;
                    } else {
                        cmx = m0x + (HH / 6.f) * (ax + kx);
                        cmy = m0y + (HH / 6.f) * (ay + ky);
                        cmz = m0z + (HH / 6.f) * (az + kz);
                        m0x = cmx; m0y = cmy; m0z = cmz;   // step complete
                    }
                    if (!(s == 1 && st == 3)) {   // final stage never re-read from smem
                        sm[nxt][ri][rj] = make_float4(cmx, cmy, cmz, 0.f);
                    }
                }
                cur = nxt;
                if (!(s == 1 && st == 3))   // no smem written at final stage
                    __syncthreads();
            }

            // probe readout (tile cells valid after every step)
            if (probemask) {
                if (step == RELAXN - 1) {
                    probe_base = m0z;
                } else if (step >= RELAXN) {
                    const float v = (m0z - probe_base) * msat;
                    const int t = step - RELAXN;
                    #pragma unroll
                    for (int p = 0; p < 4; p++)
                        if ((probemask >> p) & 1) out[t * 4 + p] = v;
                }
            }
        }

        // ---- write back owned tile (double-buffered), release flag ----
        {
            float* gmw = &g_m[ss & 1][0][0][0];
            if (is_tile) {
                const int g = gi * NXY + gj;
                __stcg(gmw + g,               m0x);
                __stcg(gmw + NXY*NXY + g,     m0y);
                __stcg(gmw + 2*NXY*NXY + g,   m0z);
            }
        }
        if (ss < NSS - 1) {
            __syncthreads();     // all tile writes done before release
            if (tid == 0) {
                __threadfence();
                atomicExch(&g_flag[me * FSTR], base + (unsigned)ss + 1u);
            }
        }
    }
}

extern "C" void kernel_launch(void* const* d_in, const int* in_sizes, int n_in,
                              void* d_out, int out_size)
{
    (void)in_sizes; (void)n_in; (void)out_size;
    mm_kernel<<<NCTA, NTHREADS>>>(
        (const float*)d_in[0],   // signal (1,256,2)
        (const float*)d_in[1],   // B_ext  (1,3,128,128)
        (const float*)d_in[2],   // Msat   (1,1,128,128)
        (const int*)d_in[3],     // src_idx (2,2)
        (const int*)d_in[4],     // probe_idx (4,2)
        (float*)d_out);          // (1,256,4)
}

// round 7
// speedup vs baseline: 1.7605x; 1.3697x over previous
#include <cuda_runtime.h>

// MMSolver: 128x128 LLG micromagnetics, 100 relax + 256 driven RK4 steps.
// Persistent kernel, 128 CTAs (8x16 tile each), superstep = 2 RK4 steps
// (8 stencil stages, halo 8) on a 24x32 region in smem, shrink-predicated,
// neighbor-local dataflow sync, float4-packed smem (R5 winner body).
// R6: the relax phase is a provable no-op when B_ext.x==0 and B_ext.z==0
// everywhere (m stays exactly y-hat: laplacian(uniform)=0, demag~m_z=0,
// m x B = 0, SOT = m x (m x yhat) = 0). A precheck kernel verifies this and
// the main kernel then skips the 100 relax steps (28% of all stages),
// falling back to the full schedule otherwise.

#define NXY 128
#define TI 8
#define TJ 16
#define HALO 8
#define RI (TI + 2*HALO)      // 24
#define RJ (TJ + 2*HALO)      // 32
#define NCTA 128
#define NTHREADS (RI*RJ)      // 768
#define RELAXN 100
#define TSIG 256
#define NSS_FULL ((RELAXN + TSIG)/2)   // 178
#define NSS_SKIP (TSIG/2)              // 128
#define FSTR 32                        // flag pad: 128B per CTA flag

#define HH      0.017595f                        // GAMMA*DT
#define CS      0.001f                           // C_SOT
#define MU0F    1.2566370614359173e-06f
#define CEXN    (2.0f*1.3e-11f/(5e-9f*5e-9f))   // 2*A_EX/DX^2

__device__ float g_m[2][3][NXY][NXY];
__device__ unsigned int g_flag[NCTA * FSTR];
__device__ int g_need[NCTA];

// Precheck: does any cell have nonzero B_ext.x or B_ext.z?
// (If not, the relax phase leaves m == y-hat exactly.)
__global__ void __launch_bounds__(128, 1)
precheck_kernel(const float* __restrict__ B_ext)
{
    __shared__ int f;
    if (threadIdx.x == 0) f = 0;
    __syncthreads();
    const int i = blockIdx.x * 128 + threadIdx.x;   // 128*128 = 16384 cells
    const float bx = B_ext[i];
    const float bz = B_ext[2 * NXY * NXY + i];
    if (bx != 0.f || bz != 0.f) f = 1;
    __syncthreads();
    if (threadIdx.x == 0) g_need[blockIdx.x] = f;
}

__global__ void __launch_bounds__(NTHREADS, 1)
mm_kernel(const float* __restrict__ signal,
          const float* __restrict__ B_ext,
          const float* __restrict__ Msat,
          const int*   __restrict__ src_idx,
          const int*   __restrict__ probe_idx,
          float*       __restrict__ out)
{
    __shared__ float4 sm[2][RI][RJ];     // (x,y,z,pad) per cell
    __shared__ unsigned int s_base;

    const int tid = threadIdx.x;
    const int me  = blockIdx.x;
    if (tid == 0) s_base = *(volatile unsigned int*)&g_flag[me * FSTR];

    // global uniform decision: run relax phase or skip it
    const int need_relax =
        __syncthreads_or(tid < NCTA ? g_need[tid] : 0);
    const int step0 = need_relax ? 0 : RELAXN;
    const int nss   = need_relax ? NSS_FULL : NSS_SKIP;

    const int ri = tid >> 5;        // region row 0..23 (warp id)
    const int rj = tid & 31;        // region col 0..31 (lane)
    const int bi = me >> 3;         // 0..15
    const int bj = me & 7;          // 0..7
    const int gi = bi * TI - HALO + ri;
    const int gj = bj * TJ - HALO + rj;
    const bool in_dom = (gi >= 0 && gi < NXY && gj >= 0 && gj < NXY);
    const int gci = min(max(gi, 0), NXY - 1);
    const int gcj = min(max(gj, 0), NXY - 1);
    const int gg  = gci * NXY + gcj;

    // neighbor region indices, clamped at the DOMAIN boundary (edge-replicate)
    const int riN = (gi <= 0)       ? ri : ri - 1;
    const int riS = (gi >= NXY - 1) ? ri : ri + 1;
    const int rjW = (gj <= 0)       ? rj : rj - 1;
    const int rjE = (gj >= NXY - 1) ? rj : rj + 1;

    // 8-neighbor CTA flag index for dataflow sync (self if out of grid)
    int nbflag = me;
    {
        const int ndi[8] = {-1,-1,-1, 0, 0, 1, 1, 1};
        const int ndj[8] = {-1, 0, 1,-1, 1,-1, 0, 1};
        if (tid < 8) {
            const int nbi = bi + ndi[tid];
            const int nbj = bj + ndj[tid];
            if (nbi >= 0 && nbi < 16 && nbj >= 0 && nbj < 8)
                nbflag = nbi * 8 + nbj;
        }
    }

    // per-cell statics
    float Bx = 0.f, By = 0.f, Bzs = 0.f, cex = 0.f, dem = 0.f, msat = 0.f;
    if (in_dom) {
        Bx   = B_ext[gg];
        By   = B_ext[NXY*NXY + gg];
        Bzs  = B_ext[2*NXY*NXY + gg];
        msat = Msat[gg];
        cex  = CEXN / msat;
        dem  = -MU0F * msat;
    }

    // src slot: last match wins (JAX .set scatter semantics)
    int srcslot = -1;
    #pragma unroll
    for (int s = 0; s < 2; s++)
        if (src_idx[2*s] == gi && src_idx[2*s + 1] == gj) srcslot = s;

    const bool is_tile = (ri >= HALO && ri < HALO + TI && rj >= HALO && rj < HALO + TJ);
    int probemask = 0;
    if (is_tile && in_dom) {
        #pragma unroll
        for (int p = 0; p < 4; p++)
            if (probe_idx[2*p] == gi && probe_idx[2*p + 1] == gj) probemask |= 1 << p;
    }
    float probe_base = 0.f;   // when relax is skipped, m0_z == 0 exactly

    // precomputed shrink-window predicate, one bit per stage q=0..7
    unsigned cmask = 0;
    #pragma unroll
    for (int q = 0; q < 8; q++)
        if (in_dom && ri > q && ri < RI - 1 - q && rj > q && rj < RJ - 1 - q)
            cmask |= 1u << q;

    __syncthreads();
    const unsigned base = s_base;

    float cmx, cmy, cmz;    // current stage value
    float m0x, m0y, m0z;    // value at start of current RK4 step
    int cur = 0;

    for (int ss = 0; ss < nss; ++ss) {
        // ---- wait for neighbors (ss>=1), then load region ----
        if (ss == 0) {
            cmx = 0.f; cmy = 1.f; cmz = 0.f;   // m_init (= post-relax state when skipping)
        } else {
            if (tid < 8) {
                const unsigned tgt = base + (unsigned)ss;
                while ((int)(*(volatile unsigned int*)&g_flag[nbflag * FSTR] - tgt) < 0) { }
                __threadfence();
            }
            __syncthreads();
            const float* gmr = &g_m[(ss - 1) & 1][0][0][0];
            cmx = __ldcg(gmr + gg);
            cmy = __ldcg(gmr + NXY*NXY + gg);
            cmz = __ldcg(gmr + 2*NXY*NXY + gg);
        }
        sm[cur][ri][rj] = make_float4(cmx, cmy, cmz, 0.f);
        m0x = cmx; m0y = cmy; m0z = cmz;

        // preload driven-field z for the 2 steps of this superstep
        float bzstep[2]; bzstep[0] = Bzs; bzstep[1] = Bzs;
        if (srcslot >= 0) {
            #pragma unroll
            for (int s = 0; s < 2; s++) {
                const int step = step0 + ss * 2 + s;
                if (step >= RELAXN)
                    bzstep[s] = __ldg(&signal[(step - RELAXN) * 2 + srcslot]);
            }
        }
        __syncthreads();

        #pragma unroll
        for (int s = 0; s < 2; ++s) {
            const int step = step0 + ss * 2 + s;
            const bool relax = (step < RELAXN);
            const float alpha = relax ? 0.5f : 0.02f;
            const float ncoef = -1.0f / (1.0f + alpha * alpha);
            const float bzd = bzstep[s];

            float ax = 0.f, ay = 0.f, az = 0.f;   // k1 + 2k2 + 2k3

            #pragma unroll
            for (int st = 0; st < 4; ++st) {
                const int q = s * 4 + st;
                const bool comp = (cmask >> q) & 1;
                const int nxt = cur ^ 1;
                if (comp) {
                    const float4 vN = sm[cur][riN][rj];
                    const float4 vS = sm[cur][riS][rj];
                    const float4 vW = sm[cur][ri][rjW];
                    const float4 vE = sm[cur][ri][rjE];
                    const float lx = (vN.x + vS.x) + (vW.x + vE.x) - 4.f * cmx;
                    const float ly = (vN.y + vS.y) + (vW.y + vE.y) - 4.f * cmy;
                    const float lz = (vN.z + vS.z) + (vW.z + vE.z) - 4.f * cmz;
                    const float bx = Bx  + cex * lx;
                    const float by = By  + cex * ly;
                    const float bz = bzd + cex * lz + dem * cmz;
                    // c = m x B
                    const float cx = cmy * bz - cmz * by;
                    const float cy = cmz * bx - cmx * bz;
                    const float cz = cmx * by - cmy * bx;
                    // d = m x c
                    const float dx = cmy * cz - cmz * cy;
                    const float dy = cmz * cx - cmx * cz;
                    const float dz = cmx * cy - cmy * cx;
                    // k = sot + ncoef*(c + alpha*d)
                    const float kx =  CS * (cmx * cmy)             + ncoef * (cx + alpha * dx);
                    const float ky = -CS * (cmx * cmx + cmz * cmz) + ncoef * (cy + alpha * dy);
                    const float kz =  CS * (cmy * cmz)             + ncoef * (cz + alpha * dz);

                    if (st < 3) {
                        const float w = (st == 0) ? 1.f : 2.f;
                        ax += w * kx; ay += w * ky; az += w * kz;
                        const float cc = (st == 2) ? HH : (0.5f * HH);
                        cmx = m0x + cc * kx;
                        cmy = m0y + cc * ky;
                        cmz = m0z + cc * kz;
                    } else {
                        cmx = m0x + (HH / 6.f) * (ax + kx);
                        cmy = m0y + (HH / 6.f) * (ay + ky);
                        cmz = m0z + (HH / 6.f) * (az + kz);
                        m0x = cmx; m0y = cmy; m0z = cmz;   // step complete
                    }
                    if (!(s == 1 && st == 3)) {   // final stage never re-read from smem
                        sm[nxt][ri][rj] = make_float4(cmx, cmy, cmz, 0.f);
                    }
                }
                cur = nxt;
                if (!(s == 1 && st == 3))   // no smem written at final stage
                    __syncthreads();
            }

            // probe readout (tile cells valid after every step)
            if (probemask) {
                if (step == RELAXN - 1) {
                    probe_base = m0z;
                } else if (step >= RELAXN) {
                    const float v = (m0z - probe_base) * msat;
                    const int t = step - RELAXN;
                    #pragma unroll
                    for (int p = 0; p < 4; p++)
                        if ((probemask >> p) & 1) out[t * 4 + p] = v;
                }
            }
        }

        // ---- write back owned tile (double-buffered), release flag ----
        {
            float* gmw = &g_m[ss & 1][0][0][0];
            if (is_tile) {
                const int g = gi * NXY + gj;
                __stcg(gmw + g,               m0x);
                __stcg(gmw + NXY*NXY + g,     m0y);
                __stcg(gmw + 2*NXY*NXY + g,   m0z);
            }
        }
        if (ss < nss - 1) {
            __syncthreads();     // all tile writes done before release
            if (tid == 0) {
                __threadfence();
                atomicExch(&g_flag[me * FSTR], base + (unsigned)ss + 1u);
            }
        }
    }
}

extern "C" void kernel_launch(void* const* d_in, const int* in_sizes, int n_in,
                              void* d_out, int out_size)
{
    (void)in_sizes; (void)n_in; (void)out_size;
    precheck_kernel<<<NCTA, 128>>>((const float*)d_in[1]);
    mm_kernel<<<NCTA, NTHREADS>>>(
        (const float*)d_in[0],   // signal (1,256,2)
        (const float*)d_in[1],   // B_ext  (1,3,128,128)
        (const float*)d_in[2],   // Msat   (1,1,128,128)
        (const int*)d_in[3],     // src_idx (2,2)
        (const int*)d_in[4],     // probe_idx (4,2)
        (float*)d_out);          // (1,256,4)
}